// round 13
// baseline (speedup 1.0000x reference)
#include <cuda_runtime.h>
#include <cuda_bf16.h>
#include <cstdint>

// Problem shapes (fixed for GCNNet_61323543052323)
#define NN   100000
#define FIN  512
#define HH   256
#define DOUT 128
#define EMAX 800000
#define NBLK ((NN + 255) / 256)

// -------------------- scratch (device globals) ------------------------------
__device__ __align__(128) float g_dinv[NN];
__device__ __align__(128) float g_hs1 [(size_t)NN * HH];
__device__ __align__(128) float g_hs2 [(size_t)NN * DOUT];
__device__ __align__(128) __nv_bfloat16 g_h1h[(size_t)NN * HH];
__device__ __align__(128) __nv_bfloat16 g_h1l[(size_t)NN * HH];
__device__ __align__(128) __nv_bfloat16 g_w1th[(size_t)HH * FIN]; // W1^T hi [N][K]
__device__ __align__(128) __nv_bfloat16 g_w1tl[(size_t)HH * FIN];
__device__ __align__(128) __nv_bfloat16 g_w2th[(size_t)DOUT * HH];
__device__ __align__(128) __nv_bfloat16 g_w2tl[(size_t)DOUT * HH];
// CSR by destination (segment bases via atomic counter; order irrelevant)
__device__ __align__(128) int g_cnt [NN];
__device__ __align__(128) int g_fill[NN];
__device__ __align__(128) int g_ptr [NN];
__device__ __align__(128) int g_csr [EMAX];
__device__ int g_total;
__device__ int g_is64;

// -------------------- helpers ----------------------------------------------
__device__ __forceinline__ uint32_t smem_u32(const void* p) {
    uint32_t a;
    asm("{ .reg .u64 t; cvta.to.shared.u64 t, %1; cvt.u32.u64 %0, t; }" : "=r"(a) : "l"(p));
    return a;
}
__device__ __forceinline__ void ldmx4(uint32_t* r, uint32_t addr) {
    asm volatile("ldmatrix.sync.aligned.m8n8.x4.shared.b16 {%0,%1,%2,%3}, [%4];"
                 : "=r"(r[0]), "=r"(r[1]), "=r"(r[2]), "=r"(r[3]) : "r"(addr));
}
__device__ __forceinline__ void mma_bf16(float* d, const uint32_t* a, const uint32_t* b) {
    asm volatile(
        "mma.sync.aligned.m16n8k16.row.col.f32.bf16.bf16.f32 "
        "{%0,%1,%2,%3}, {%4,%5,%6,%7}, {%8,%9}, {%0,%1,%2,%3};"
        : "+f"(d[0]), "+f"(d[1]), "+f"(d[2]), "+f"(d[3])
        : "r"(a[0]), "r"(a[1]), "r"(a[2]), "r"(a[3]), "r"(b[0]), "r"(b[1]));
}
__device__ __forceinline__ void cp16(uint32_t dst, const void* src) {
    asm volatile("cp.async.cg.shared.global [%0], [%1], 16;" :: "r"(dst), "l"(src));
}
__device__ __forceinline__ void cp16p(uint32_t dst, const void* src, int bytes) {
    asm volatile("cp.async.cg.shared.global [%0], [%1], 16, %2;"
                 :: "r"(dst), "l"(src), "r"(bytes));   // bytes==0 -> zero fill
}
__device__ __forceinline__ void cp_commit() { asm volatile("cp.async.commit_group;"); }
__device__ __forceinline__ void cp_wait1()  { asm volatile("cp.async.wait_group 1;" ::: "memory"); }

__device__ __forceinline__ void split_bf16(float v, unsigned short& h, unsigned short& l) {
    __nv_bfloat16 bh = __float2bfloat16_rn(v);
    float r = v - __bfloat162float(bh);
    h = __bfloat16_as_ushort(bh);
    l = __bfloat16_as_ushort(__float2bfloat16_rn(r));
}
__device__ __forceinline__ void split8(const float4& f0, const float4& f1, uint4& H, uint4& L) {
    unsigned short h[8], l[8];
    split_bf16(f0.x, h[0], l[0]); split_bf16(f0.y, h[1], l[1]);
    split_bf16(f0.z, h[2], l[2]); split_bf16(f0.w, h[3], l[3]);
    split_bf16(f1.x, h[4], l[4]); split_bf16(f1.y, h[5], l[5]);
    split_bf16(f1.z, h[6], l[6]); split_bf16(f1.w, h[7], l[7]);
    H = make_uint4((uint32_t)h[0] | ((uint32_t)h[1] << 16), (uint32_t)h[2] | ((uint32_t)h[3] << 16),
                   (uint32_t)h[4] | ((uint32_t)h[5] << 16), (uint32_t)h[6] | ((uint32_t)h[7] << 16));
    L = make_uint4((uint32_t)l[0] | ((uint32_t)l[1] << 16), (uint32_t)l[2] | ((uint32_t)l[3] << 16),
                   (uint32_t)l[4] | ((uint32_t)l[5] << 16), (uint32_t)l[6] | ((uint32_t)l[7] << 16));
}

// -------------------- edge index access ------------------------------------
__device__ __forceinline__ int edge_idx(const void* __restrict__ ei_raw,
                                        int E, int which, int e) {
    long long v;
    if (g_is64) v = ((const long long*)ei_raw)[(size_t)which * E + e];
    else        v = ((const int*)ei_raw)[(size_t)which * E + e];
    unsigned u = (unsigned)v;
    return (u < NN) ? (int)u : 0;
}

// -------------------- fused preproc 0: zero + detect + both wsplits --------
__global__ void k_pre0(const void* __restrict__ ei_raw, int E,
                       const float* __restrict__ W1, const float* __restrict__ W2) {
    int i = blockIdx.x * blockDim.x + threadIdx.x;
    if (i < NN) { g_cnt[i] = 0; g_fill[i] = 0; }
    if (i == 0) g_total = 0;
    if (i < FIN * HH) {
        int k = i / HH, n = i % HH;
        unsigned short h, l;
        split_bf16(W1[i], h, l);
        g_w1th[(size_t)n * FIN + k] = __ushort_as_bfloat16(h);
        g_w1tl[(size_t)n * FIN + k] = __ushort_as_bfloat16(l);
    }
    if (i < HH * DOUT) {
        int k = i / DOUT, n = i % DOUT;
        unsigned short h, l;
        split_bf16(W2[i], h, l);
        g_w2th[(size_t)n * HH + k] = __ushort_as_bfloat16(h);
        g_w2tl[(size_t)n * HH + k] = __ushort_as_bfloat16(l);
    }
    if (blockIdx.x == 0) {                     // dtype detect
        const long long* p = (const long long*)ei_raw;
        int bad = 0;
        int n = (E < 1024) ? E : 1024;
        for (int j = threadIdx.x; j < n; j += 256) {
            long long v = p[j];
            if (v < 0 || v >= NN) bad = 1;
        }
        bad = __syncthreads_or(bad);
        if (threadIdx.x == 0) g_is64 = !bad;
    }
}
__global__ void k_hist(const void* __restrict__ ei, int E) {
    int e = blockIdx.x * blockDim.x + threadIdx.x;
    if (e < E) atomicAdd(&g_cnt[edge_idx(ei, E, 1, e)], 1);
}
__global__ void k_ptrdinv() {
    int i = blockIdx.x * blockDim.x + threadIdx.x;
    if (i < NN) {
        int c = g_cnt[i];
        g_ptr[i]  = atomicAdd(&g_total, c);
        g_dinv[i] = rsqrtf(1.0f + (float)c);
    }
}
__global__ void k_fill(const void* __restrict__ ei, int E) {
    int e = blockIdx.x * blockDim.x + threadIdx.x;
    if (e >= E) return;
    int src = edge_idx(ei, E, 0, e);
    int dst = edge_idx(ei, E, 1, e);
    int slot = g_ptr[dst] + atomicAdd(&g_fill[dst], 1);
    if (slot < EMAX) g_csr[slot] = src;
}

// -------------------- bf16 split-3 GEMM via mma.sync (HMMA) ----------------
// C = (A @ W) * dinv[row].  Block 128x128xBK32, 8 warps (4m x 2n), warp 32x64.
// 3-stage cp.async pipeline (wait -> barrier -> compute); 64B rows + XOR swizzle.
template <int LAYER>
__global__ __launch_bounds__(256, 2)
void k_gemm_mma(const float* __restrict__ x) {
    constexpr int K  = (LAYER == 1) ? FIN : HH;
    constexpr int N  = (LAYER == 1) ? HH  : DOUT;
    constexpr int M  = NN;
    constexpr int BK = 32;
    constexpr int NIT = K / BK;
    // stage layout (32 KB): A_HI 0, A_LO 8192, B_HI 16384, B_LO 24576
    constexpr int STG = 32768;

    extern __shared__ char smem[];
    const uint32_t sb = smem_u32(smem);

    const __nv_bfloat16* __restrict__ Wth = (LAYER == 1) ? g_w1th : g_w2th;
    const __nv_bfloat16* __restrict__ Wtl = (LAYER == 1) ? g_w1tl : g_w2tl;
    float* __restrict__ C0 = (LAYER == 1) ? g_hs1 : g_hs2;

    const int tid  = threadIdx.x;
    const int lane = tid & 31;
    const int wid  = tid >> 5;
    const int wm   = (wid & 3) * 32;
    const int wn   = (wid >> 2) * 64;
    const int m0   = blockIdx.y * 128;
    const int n0   = blockIdx.x * 128;

    // ldmatrix per-lane bases (row*64) + swizzle keys
    const int a_rs = lane & 15;
    const int a_ch = lane >> 4;
    uint32_t a_off[2]; int a_sw[2];
#pragma unroll
    for (int mt = 0; mt < 2; mt++) {
        int row = wm + mt * 16 + a_rs;
        a_off[mt] = (uint32_t)row * 64;
        a_sw[mt]  = (row >> 1) & 3;
    }
    const int b_row = (lane & 7) + (lane >> 4) * 8;
    const int b_ch  = (lane >> 3) & 1;
    uint32_t b_off[4]; int b_sw[4];
#pragma unroll
    for (int p = 0; p < 4; p++) {
        int row = wn + p * 16 + b_row;
        b_off[p] = 16384u + (uint32_t)row * 64;
        b_sw[p]  = (row >> 1) & 3;
    }

    float acc[2][8][4];
#pragma unroll
    for (int i = 0; i < 2; i++)
#pragma unroll
        for (int j = 0; j < 8; j++)
#pragma unroll
            for (int q = 0; q < 4; q++) acc[i][j][q] = 0.0f;

    float4 fa[4];                         // layer-1 A register staging

    // writer mapping: row = lin>>2, c4 = lin&3; phys = c4 ^ ((row>>1)&3)
    auto wr_off = [&](int s) {
        int lin = s * 256 + tid;
        int row = lin >> 2, c4 = lin & 3;
        return (uint32_t)(row * 64 + ((c4 ^ ((row >> 1) & 3)) << 4));
    };

    auto cpa = [&](int it, int st) {
        if (it < NIT) {
            const int k0 = it * BK;
            const uint32_t base = sb + st * STG;
#pragma unroll
            for (int s = 0; s < 2; s++) {
                int lin = s * 256 + tid;
                int row = lin >> 2, c4 = lin & 3;
                uint32_t off = wr_off(s);
                if constexpr (LAYER == 2) {
                    int gm = m0 + row;
                    int ok = (gm < M) ? 16 : 0;
                    cp16p(base + off,
                          (const unsigned short*)g_h1h + (size_t)gm * K + k0 + c4 * 8, ok);
                    cp16p(base + 8192 + off,
                          (const unsigned short*)g_h1l + (size_t)gm * K + k0 + c4 * 8, ok);
                }
                cp16(base + 16384 + off,
                     (const unsigned short*)Wth + (size_t)(n0 + row) * K + k0 + c4 * 8);
                cp16(base + 24576 + off,
                     (const unsigned short*)Wtl + (size_t)(n0 + row) * K + k0 + c4 * 8);
            }
        }
        cp_commit();                      // one group per call (empty at tail)
    };

    auto ldgA = [&](int it) {             // layer-1 only: fp32 A into regs
        if constexpr (LAYER == 1) {
            if (it < NIT) {
                const int k0 = it * BK;
#pragma unroll
                for (int s = 0; s < 2; s++) {
                    int lin = s * 256 + tid;
                    int row = lin >> 2, c4 = lin & 3;
                    int gm = m0 + row;
                    if (gm < M) {
                        fa[s * 2]     = *(const float4*)&x[(size_t)gm * K + k0 + c4 * 8];
                        fa[s * 2 + 1] = *(const float4*)&x[(size_t)gm * K + k0 + c4 * 8 + 4];
                    } else {
                        fa[s * 2] = fa[s * 2 + 1] = make_float4(0.f, 0.f, 0.f, 0.f);
                    }
                }
            }
        }
    };

    auto stsA = [&](int it, int st) {     // layer-1 only: split + store A
        if constexpr (LAYER == 1) {
            if (it < NIT) {
                char* base = smem + st * STG;
#pragma unroll
                for (int s = 0; s < 2; s++) {
                    uint32_t off = wr_off(s);
                    uint4 H, L;
                    split8(fa[s * 2], fa[s * 2 + 1], H, L);
                    *(uint4*)(base + off) = H;
                    *(uint4*)(base + 8192 + off) = L;
                }
            }
        }
    };

    auto compute = [&](int st) {
        const uint32_t so = sb + st * STG;
#pragma unroll
        for (int ks = 0; ks < 2; ks++) {
            uint32_t ah[2][4], al[2][4], bf[8][2];
#pragma unroll
            for (int mt = 0; mt < 2; mt++) {
                uint32_t ad = so + a_off[mt] +
                              (uint32_t)(((2 * ks + a_ch) ^ a_sw[mt]) << 4);
                ldmx4(ah[mt], ad);
                ldmx4(al[mt], ad + 8192);
            }
#pragma unroll
            for (int p = 0; p < 4; p++) {
                uint32_t bd = so + b_off[p] +
                              (uint32_t)(((2 * ks + b_ch) ^ b_sw[p]) << 4);
                uint32_t r[4];
                ldmx4(r, bd);
                bf[2 * p][0] = r[0]; bf[2 * p][1] = r[1];
                bf[2 * p + 1][0] = r[2]; bf[2 * p + 1][1] = r[3];
            }
#pragma unroll
            for (int mt = 0; mt < 2; mt++)
#pragma unroll
                for (int nt = 0; nt < 8; nt++) mma_bf16(acc[mt][nt], ah[mt], bf[nt]);
#pragma unroll
            for (int mt = 0; mt < 2; mt++)
#pragma unroll
                for (int nt = 0; nt < 8; nt++) mma_bf16(acc[mt][nt], al[mt], bf[nt]);
#pragma unroll
            for (int p = 0; p < 4; p++) {
                uint32_t bd = so + b_off[p] + 8192u +
                              (uint32_t)(((2 * ks + b_ch) ^ b_sw[p]) << 4);
                uint32_t r[4];
                ldmx4(r, bd);
                bf[2 * p][0] = r[0]; bf[2 * p][1] = r[1];
                bf[2 * p + 1][0] = r[2]; bf[2 * p + 1][1] = r[3];
            }
#pragma unroll
            for (int mt = 0; mt < 2; mt++)
#pragma unroll
                for (int nt = 0; nt < 8; nt++) mma_bf16(acc[mt][nt], ah[mt], bf[nt]);
        }
    };

    // prologue: stages 0 and 1 (groups 1 and 2)
    cpa(0, 0);  ldgA(0); stsA(0, 0);
    cpa(1, 1);  ldgA(1); stsA(1, 1);

    int cur = 0;
    for (int it = 0; it < NIT; it++) {
        cp_wait1();           // stage cur's async group complete (this thread)
        __syncthreads();      // ...and visible to ALL threads; also fences stage reuse
        int it2 = it + 2;
        int st2 = (cur + 2) % 3;
        cpa(it2, st2);        // async into stage (it-1)%3: readers done pre-sync
        ldgA(it2);
        compute(cur);
        stsA(it2, st2);       // STS A: visible to its reader via the next 2 syncs
        cur = (cur + 1) % 3;
    }

    // direct-register epilogue
#pragma unroll
    for (int mt = 0; mt < 2; mt++) {
        int r0 = wm + mt * 16 + (lane >> 2);
        int gm0 = m0 + r0;
        int gm1 = gm0 + 8;
        float s0 = (gm0 < M) ? g_dinv[gm0] : 0.0f;
        float s1 = (gm1 < M) ? g_dinv[gm1] : 0.0f;
#pragma unroll
        for (int nt = 0; nt < 8; nt++) {
            int col = n0 + wn + nt * 8 + (lane & 3) * 2;
            if (gm0 < M)
                *(float2*)&C0[(size_t)gm0 * N + col] =
                    make_float2(acc[mt][nt][0] * s0, acc[mt][nt][1] * s0);
            if (gm1 < M)
                *(float2*)&C0[(size_t)gm1 * N + col] =
                    make_float2(acc[mt][nt][2] * s1, acc[mt][nt][3] * s1);
        }
    }
}

// -------------------- fused gather-aggregate + bias (+relu/split) ----------
template <int LAYER>
__global__ void k_gather(const float* __restrict__ bias, float* __restrict__ out_param) {
    constexpr int NC = (LAYER == 1) ? HH : DOUT;
    constexpr int CH = NC / 4;
    const float* __restrict__ hs = (LAYER == 1) ? g_hs1 : g_hs2;

    int gtid = blockIdx.x * blockDim.x + threadIdx.x;
    int node = gtid / CH;
    if (node >= NN) return;
    int c = (gtid % CH) * 4;

    float4 v = *(const float4*)&hs[(size_t)node * NC + c];   // self loop
    int beg = g_ptr[node];
    int end = beg + g_cnt[node];
    int j = beg;
    for (; j + 1 < end; j += 2) {
        int s0 = g_csr[j], s1 = g_csr[j + 1];
        float4 a = *(const float4*)&hs[(size_t)s0 * NC + c];
        float4 b = *(const float4*)&hs[(size_t)s1 * NC + c];
        v.x += a.x + b.x; v.y += a.y + b.y; v.z += a.z + b.z; v.w += a.w + b.w;
    }
    if (j < end) {
        int s0 = g_csr[j];
        float4 a = *(const float4*)&hs[(size_t)s0 * NC + c];
        v.x += a.x; v.y += a.y; v.z += a.z; v.w += a.w;
    }

    float s = g_dinv[node];
    float4 b = *(const float4*)&bias[c];
    float4 r = make_float4(fmaf(v.x, s, b.x), fmaf(v.y, s, b.y),
                           fmaf(v.z, s, b.z), fmaf(v.w, s, b.w));
    if (LAYER == 1) {
        r.x = fmaxf(r.x, 0.f); r.y = fmaxf(r.y, 0.f);
        r.z = fmaxf(r.z, 0.f); r.w = fmaxf(r.w, 0.f);
        unsigned short h0, h1, h2, h3, l0, l1, l2, l3;
        split_bf16(r.x, h0, l0); split_bf16(r.y, h1, l1);
        split_bf16(r.z, h2, l2); split_bf16(r.w, h3, l3);
        uint2 uh = make_uint2((uint32_t)h0 | ((uint32_t)h1 << 16),
                              (uint32_t)h2 | ((uint32_t)h3 << 16));
        uint2 ul = make_uint2((uint32_t)l0 | ((uint32_t)l1 << 16),
                              (uint32_t)l2 | ((uint32_t)l3 << 16));
        *(uint2*)((unsigned short*)g_h1h + (size_t)node * NC + c) = uh;
        *(uint2*)((unsigned short*)g_h1l + (size_t)node * NC + c) = ul;
    } else {
        *(float4*)&out_param[(size_t)node * NC + c] = r;
    }
}

// ---------------------------------------------------------------------------
extern "C" void kernel_launch(void* const* d_in, const int* in_sizes, int n_in,
                              void* d_out, int out_size) {
    const float* x  = (const float*)d_in[0];
    const void*  ei = d_in[1];
    const float* W1 = (const float*)d_in[2];
    const float* b1 = (const float*)d_in[3];
    const float* W2 = (const float*)d_in[4];
    const float* b2 = (const float*)d_in[5];
    float*       out = (float*)d_out;

    const int E = in_sizes[1] / 2;
    const int MB = (NN + 127) / 128;
    const int SMEM = 3 * 32768;                       // 98304 per CTA, 2 CTAs/SM
    const int PRE0_BLK = (FIN * HH + 255) / 256;

    cudaFuncSetAttribute(k_gemm_mma<1>, cudaFuncAttributeMaxDynamicSharedMemorySize, SMEM);
    cudaFuncSetAttribute(k_gemm_mma<2>, cudaFuncAttributeMaxDynamicSharedMemorySize, SMEM);

    // preproc
    k_pre0   <<<PRE0_BLK, 256>>>(ei, E, W1, W2);
    k_hist   <<<(E + 255) / 256, 256>>>(ei, E);
    k_ptrdinv<<<NBLK, 256>>>();

    // layer 1 (GEMM independent of CSR fill)
    k_gemm_mma<1><<<dim3(HH / 128, MB), 256, SMEM>>>(x);
    k_fill   <<<(E + 255) / 256, 256>>>(ei, E);
    k_gather<1><<<(NN * (HH / 4) + 255) / 256, 256>>>(b1, nullptr);
    // layer 2
    k_gemm_mma<2><<<dim3(DOUT / 128, MB), 256, SMEM>>>(nullptr);
    k_gather<2><<<(NN * (DOUT / 4) + 255) / 256, 256>>>(b2, out);
}

// round 14
// speedup vs baseline: 1.6468x; 1.6468x over previous
#include <cuda_runtime.h>
#include <cuda_fp16.h>
#include <cstdint>

// Problem shapes (fixed for GCNNet_61323543052323)
#define NN   100000
#define FIN  512
#define HH   256
#define DOUT 128
#define EMAX 800000
#define NBLK ((NN + 255) / 256)

// -------------------- scratch (device globals) ------------------------------
__device__ __align__(128) float g_dinv[NN];
__device__ __align__(128) float g_hs1 [(size_t)NN * HH];
__device__ __align__(128) float g_hs2 [(size_t)NN * DOUT];
__device__ __align__(128) __half g_h1  [(size_t)NN * HH];        // h1 (fp16, single)
__device__ __align__(128) __half g_w1th[(size_t)HH * FIN];       // W1^T hi [N][K]
__device__ __align__(128) __half g_w1tl[(size_t)HH * FIN];       // W1^T lo (residual)
__device__ __align__(128) __half g_w2th[(size_t)DOUT * HH];
__device__ __align__(128) __half g_w2tl[(size_t)DOUT * HH];
// CSR by destination (segment bases via atomic counter; order irrelevant)
__device__ __align__(128) int g_cnt [NN];
__device__ __align__(128) int g_fill[NN];
__device__ __align__(128) int g_ptr [NN];
__device__ __align__(128) int g_csr [EMAX];
__device__ int g_total;
__device__ int g_is64;

// -------------------- helpers ----------------------------------------------
__device__ __forceinline__ uint32_t smem_u32(const void* p) {
    uint32_t a;
    asm("{ .reg .u64 t; cvta.to.shared.u64 t, %1; cvt.u32.u64 %0, t; }" : "=r"(a) : "l"(p));
    return a;
}
__device__ __forceinline__ void ldmx4(uint32_t* r, uint32_t addr) {
    asm volatile("ldmatrix.sync.aligned.m8n8.x4.shared.b16 {%0,%1,%2,%3}, [%4];"
                 : "=r"(r[0]), "=r"(r[1]), "=r"(r[2]), "=r"(r[3]) : "r"(addr));
}
__device__ __forceinline__ void mma_fp16(float* d, const uint32_t* a, const uint32_t* b) {
    asm volatile(
        "mma.sync.aligned.m16n8k16.row.col.f32.f16.f16.f32 "
        "{%0,%1,%2,%3}, {%4,%5,%6,%7}, {%8,%9}, {%0,%1,%2,%3};"
        : "+f"(d[0]), "+f"(d[1]), "+f"(d[2]), "+f"(d[3])
        : "r"(a[0]), "r"(a[1]), "r"(a[2]), "r"(a[3]), "r"(b[0]), "r"(b[1]));
}
__device__ __forceinline__ void cp16(uint32_t dst, const void* src) {
    asm volatile("cp.async.cg.shared.global [%0], [%1], 16;" :: "r"(dst), "l"(src));
}
__device__ __forceinline__ void cp16p(uint32_t dst, const void* src, int bytes) {
    asm volatile("cp.async.cg.shared.global [%0], [%1], 16, %2;"
                 :: "r"(dst), "l"(src), "r"(bytes));   // bytes==0 -> zero fill
}
__device__ __forceinline__ void cp_commit() { asm volatile("cp.async.commit_group;"); }
__device__ __forceinline__ void cp_wait0()  { asm volatile("cp.async.wait_group 0;" ::: "memory"); }

// pack 8 floats -> 8 fp16 (uint4)
__device__ __forceinline__ uint4 pack8h(const float4& f0, const float4& f1) {
    __half2 a = __float22half2_rn(make_float2(f0.x, f0.y));
    __half2 b = __float22half2_rn(make_float2(f0.z, f0.w));
    __half2 c = __float22half2_rn(make_float2(f1.x, f1.y));
    __half2 d = __float22half2_rn(make_float2(f1.z, f1.w));
    return make_uint4(*(uint32_t*)&a, *(uint32_t*)&b, *(uint32_t*)&c, *(uint32_t*)&d);
}

// -------------------- edge index access ------------------------------------
__device__ __forceinline__ int edge_idx(const void* __restrict__ ei_raw,
                                        int E, int which, int e) {
    long long v;
    if (g_is64) v = ((const long long*)ei_raw)[(size_t)which * E + e];
    else        v = ((const int*)ei_raw)[(size_t)which * E + e];
    unsigned u = (unsigned)v;
    return (u < NN) ? (int)u : 0;
}

// -------------------- fused preproc 0: zero + detect + both W splits -------
__global__ void k_pre0(const void* __restrict__ ei_raw, int E,
                       const float* __restrict__ W1, const float* __restrict__ W2) {
    int i = blockIdx.x * blockDim.x + threadIdx.x;
    if (i < NN) { g_cnt[i] = 0; g_fill[i] = 0; }
    if (i == 0) g_total = 0;
    if (i < FIN * HH) {
        int k = i / HH, n = i % HH;
        float w = W1[i];
        __half h = __float2half_rn(w);
        __half l = __float2half_rn(w - __half2float(h));
        g_w1th[(size_t)n * FIN + k] = h;
        g_w1tl[(size_t)n * FIN + k] = l;
    }
    if (i < HH * DOUT) {
        int k = i / DOUT, n = i % DOUT;
        float w = W2[i];
        __half h = __float2half_rn(w);
        __half l = __float2half_rn(w - __half2float(h));
        g_w2th[(size_t)n * HH + k] = h;
        g_w2tl[(size_t)n * HH + k] = l;
    }
    if (blockIdx.x == 0) {                     // dtype detect
        const long long* p = (const long long*)ei_raw;
        int bad = 0;
        int n = (E < 1024) ? E : 1024;
        for (int j = threadIdx.x; j < n; j += 256) {
            long long v = p[j];
            if (v < 0 || v >= NN) bad = 1;
        }
        bad = __syncthreads_or(bad);
        if (threadIdx.x == 0) g_is64 = !bad;
    }
}
__global__ void k_hist(const void* __restrict__ ei, int E) {
    int e = blockIdx.x * blockDim.x + threadIdx.x;
    if (e < E) atomicAdd(&g_cnt[edge_idx(ei, E, 1, e)], 1);
}
__global__ void k_ptrdinv() {
    int i = blockIdx.x * blockDim.x + threadIdx.x;
    if (i < NN) {
        int c = g_cnt[i];
        g_ptr[i]  = atomicAdd(&g_total, c);
        g_dinv[i] = rsqrtf(1.0f + (float)c);
    }
}
__global__ void k_fill(const void* __restrict__ ei, int E) {
    int e = blockIdx.x * blockDim.x + threadIdx.x;
    if (e >= E) return;
    int src = edge_idx(ei, E, 0, e);
    int dst = edge_idx(ei, E, 1, e);
    int slot = g_ptr[dst] + atomicAdd(&g_fill[dst], 1);
    if (slot < EMAX) g_csr[slot] = src;
}

// -------------------- fp16 GEMM via mma.sync (HMMA) ------------------------
// C = (A @ W) * dinv[row], W exact via hi+lo split, A single fp16.
// D = Ah@Bh + Ah@Bl.  Block 128x128xBK32, 8 warps (4m x 2n), warp 32x64.
// 2-stage pipeline, R10-proven ordering. Stage 30720B: A 0, B_HI 10240, B_LO 20480.
template <int LAYER>
__global__ __launch_bounds__(256, 2)
void k_gemm_mma(const float* __restrict__ x) {
    constexpr int K  = (LAYER == 1) ? FIN : HH;
    constexpr int N  = (LAYER == 1) ? HH  : DOUT;
    constexpr int M  = NN;
    constexpr int BK = 32;
    constexpr int NIT = K / BK;
    constexpr int ASTR = 80;                 // 64B row + 16B pad (R10-proven)
    constexpr int BHo = 10240, BLo = 20480;
    constexpr int STG = 30720;

    extern __shared__ char smem[];
    const uint32_t sb = smem_u32(smem);

    const __half* __restrict__ Wth = (LAYER == 1) ? g_w1th : g_w2th;
    const __half* __restrict__ Wtl = (LAYER == 1) ? g_w1tl : g_w2tl;
    float* __restrict__ C0 = (LAYER == 1) ? g_hs1 : g_hs2;

    const int tid  = threadIdx.x;
    const int lane = tid & 31;
    const int wid  = tid >> 5;
    const int wm   = (wid & 3) * 32;
    const int wn   = (wid >> 2) * 64;
    const int m0   = blockIdx.y * 128;
    const int n0   = blockIdx.x * 128;

    const int a_rs = (lane & 7) + ((lane >> 3) & 1) * 8;
    const int a_ch = lane >> 4;
    uint32_t a_base[2];
#pragma unroll
    for (int mt = 0; mt < 2; mt++)
        a_base[mt] = sb + (uint32_t)(wm + mt * 16 + a_rs) * ASTR + a_ch * 16;
    const int b_row = (lane & 7) + (lane >> 4) * 8;
    const int b_ch  = (lane >> 3) & 1;
    uint32_t b_base[4];
#pragma unroll
    for (int p = 0; p < 4; p++)
        b_base[p] = sb + BHo + (uint32_t)(wn + p * 16 + b_row) * ASTR + b_ch * 16;

    float acc[2][8][4];
#pragma unroll
    for (int i = 0; i < 2; i++)
#pragma unroll
        for (int j = 0; j < 8; j++)
#pragma unroll
            for (int q = 0; q < 4; q++) acc[i][j][q] = 0.0f;

    float4 fa[4];                         // layer-1 A register staging

    // async staging: B hi/lo (both layers) + A (layer 2, fp16 single)
    auto cpa = [&](int it, int st) {
        const int k0 = it * BK;
        const uint32_t base = sb + st * STG;
#pragma unroll
        for (int s = 0; s < 2; s++) {
            int lin = s * 256 + tid;
            int row = lin >> 2, c4 = lin & 3;
            uint32_t off = (uint32_t)row * ASTR + c4 * 16;
            if constexpr (LAYER == 2) {
                int gm = m0 + row;
                int ok = (gm < M) ? 16 : 0;
                cp16p(base + off,
                      (const unsigned short*)g_h1 + (size_t)gm * K + k0 + c4 * 8, ok);
            }
            cp16(base + BHo + off,
                 (const unsigned short*)Wth + (size_t)(n0 + row) * K + k0 + c4 * 8);
            cp16(base + BLo + off,
                 (const unsigned short*)Wtl + (size_t)(n0 + row) * K + k0 + c4 * 8);
        }
        cp_commit();
    };

    auto ldgA = [&](int it) {             // layer-1 only: fp32 A into regs
        if constexpr (LAYER == 1) {
            const int k0 = it * BK;
#pragma unroll
            for (int s = 0; s < 2; s++) {
                int lin = s * 256 + tid;
                int row = lin >> 2, c4 = lin & 3;
                int gm = m0 + row;
                if (gm < M) {
                    fa[s * 2]     = *(const float4*)&x[(size_t)gm * K + k0 + c4 * 8];
                    fa[s * 2 + 1] = *(const float4*)&x[(size_t)gm * K + k0 + c4 * 8 + 4];
                } else {
                    fa[s * 2] = fa[s * 2 + 1] = make_float4(0.f, 0.f, 0.f, 0.f);
                }
            }
        }
    };

    auto stsA = [&](int st) {             // layer-1 only: fp32 -> fp16, store A
        if constexpr (LAYER == 1) {
            char* base = smem + st * STG;
#pragma unroll
            for (int s = 0; s < 2; s++) {
                int lin = s * 256 + tid;
                int row = lin >> 2, c4 = lin & 3;
                uint32_t off = (uint32_t)row * ASTR + c4 * 16;
                *(uint4*)(base + off) = pack8h(fa[s * 2], fa[s * 2 + 1]);
            }
        }
    };

    auto compute = [&](int st) {
        const uint32_t so = st * STG;
#pragma unroll
        for (int ks = 0; ks < 2; ks++) {
            uint32_t ah[2][4], bf[8][2];
            ldmx4(ah[0], a_base[0] + so + ks * 32);
            ldmx4(ah[1], a_base[1] + so + ks * 32);
#pragma unroll
            for (int p = 0; p < 4; p++) {
                uint32_t r[4];
                ldmx4(r, b_base[p] + so + ks * 32);
                bf[2 * p][0] = r[0]; bf[2 * p][1] = r[1];
                bf[2 * p + 1][0] = r[2]; bf[2 * p + 1][1] = r[3];
            }
#pragma unroll
            for (int mt = 0; mt < 2; mt++)
#pragma unroll
                for (int nt = 0; nt < 8; nt++) mma_fp16(acc[mt][nt], ah[mt], bf[nt]);
#pragma unroll
            for (int p = 0; p < 4; p++) {
                uint32_t r[4];
                ldmx4(r, b_base[p] + so + (BLo - BHo) + ks * 32);
                bf[2 * p][0] = r[0]; bf[2 * p][1] = r[1];
                bf[2 * p + 1][0] = r[2]; bf[2 * p + 1][1] = r[3];
            }
#pragma unroll
            for (int mt = 0; mt < 2; mt++)
#pragma unroll
                for (int nt = 0; nt < 8; nt++) mma_fp16(acc[mt][nt], ah[mt], bf[nt]);
        }
    };

    // R10-proven pipeline: cpa -> ldg -> compute -> sts -> wait0 -> sync
    cpa(0, 0);
    ldgA(0);
    stsA(0);
    cp_wait0();
    __syncthreads();

    int cur = 0;
    for (int it = 1; it < NIT; it++) {
        cpa(it, cur ^ 1);      // async loads retire under compute
        ldgA(it);
        compute(cur);
        stsA(cur ^ 1);
        cp_wait0();
        __syncthreads();
        cur ^= 1;
    }
    compute(cur);

    // direct-register epilogue (quad-contiguous float2 stores)
#pragma unroll
    for (int mt = 0; mt < 2; mt++) {
        int r0 = wm + mt * 16 + (lane >> 2);
        int gm0 = m0 + r0;
        int gm1 = gm0 + 8;
        float s0 = (gm0 < M) ? g_dinv[gm0] : 0.0f;
        float s1 = (gm1 < M) ? g_dinv[gm1] : 0.0f;
#pragma unroll
        for (int nt = 0; nt < 8; nt++) {
            int col = n0 + wn + nt * 8 + (lane & 3) * 2;
            if (gm0 < M)
                *(float2*)&C0[(size_t)gm0 * N + col] =
                    make_float2(acc[mt][nt][0] * s0, acc[mt][nt][1] * s0);
            if (gm1 < M)
                *(float2*)&C0[(size_t)gm1 * N + col] =
                    make_float2(acc[mt][nt][2] * s1, acc[mt][nt][3] * s1);
        }
    }
}

// -------------------- fused gather-aggregate + bias (+relu/fp16) -----------
template <int LAYER>
__global__ void k_gather(const float* __restrict__ bias, float* __restrict__ out_param) {
    constexpr int NC = (LAYER == 1) ? HH : DOUT;
    constexpr int CH = NC / 4;
    const float* __restrict__ hs = (LAYER == 1) ? g_hs1 : g_hs2;

    int gtid = blockIdx.x * blockDim.x + threadIdx.x;
    int node = gtid / CH;
    if (node >= NN) return;
    int c = (gtid % CH) * 4;

    float4 v = *(const float4*)&hs[(size_t)node * NC + c];   // self loop
    int beg = g_ptr[node];
    int end = beg + g_cnt[node];
    int j = beg;
    for (; j + 1 < end; j += 2) {
        int s0 = g_csr[j], s1 = g_csr[j + 1];
        float4 a = *(const float4*)&hs[(size_t)s0 * NC + c];
        float4 b = *(const float4*)&hs[(size_t)s1 * NC + c];
        v.x += a.x + b.x; v.y += a.y + b.y; v.z += a.z + b.z; v.w += a.w + b.w;
    }
    if (j < end) {
        int s0 = g_csr[j];
        float4 a = *(const float4*)&hs[(size_t)s0 * NC + c];
        v.x += a.x; v.y += a.y; v.z += a.z; v.w += a.w;
    }

    float s = g_dinv[node];
    float4 b = *(const float4*)&bias[c];
    float4 r = make_float4(fmaf(v.x, s, b.x), fmaf(v.y, s, b.y),
                           fmaf(v.z, s, b.z), fmaf(v.w, s, b.w));
    if (LAYER == 1) {
        r.x = fmaxf(r.x, 0.f); r.y = fmaxf(r.y, 0.f);
        r.z = fmaxf(r.z, 0.f); r.w = fmaxf(r.w, 0.f);
        __half2 h0 = __float22half2_rn(make_float2(r.x, r.y));
        __half2 h1 = __float22half2_rn(make_float2(r.z, r.w));
        *(uint2*)((unsigned short*)g_h1 + (size_t)node * NC + c) =
            make_uint2(*(uint32_t*)&h0, *(uint32_t*)&h1);
    } else {
        *(float4*)&out_param[(size_t)node * NC + c] = r;
    }
}

// ---------------------------------------------------------------------------
extern "C" void kernel_launch(void* const* d_in, const int* in_sizes, int n_in,
                              void* d_out, int out_size) {
    const float* x  = (const float*)d_in[0];
    const void*  ei = d_in[1];
    const float* W1 = (const float*)d_in[2];
    const float* b1 = (const float*)d_in[3];
    const float* W2 = (const float*)d_in[4];
    const float* b2 = (const float*)d_in[5];
    float*       out = (float*)d_out;

    const int E = in_sizes[1] / 2;
    const int MB = (NN + 127) / 128;
    const int SMEM = 2 * 30720;                       // 61440 per CTA, 2 CTAs/SM
    const int PRE0_BLK = (FIN * HH + 255) / 256;

    cudaFuncSetAttribute(k_gemm_mma<1>, cudaFuncAttributeMaxDynamicSharedMemorySize, SMEM);
    cudaFuncSetAttribute(k_gemm_mma<2>, cudaFuncAttributeMaxDynamicSharedMemorySize, SMEM);

    // preproc
    k_pre0   <<<PRE0_BLK, 256>>>(ei, E, W1, W2);
    k_hist   <<<(E + 255) / 256, 256>>>(ei, E);
    k_ptrdinv<<<NBLK, 256>>>();

    // layer 1 (GEMM independent of CSR fill)
    k_gemm_mma<1><<<dim3(HH / 128, MB), 256, SMEM>>>(x);
    k_fill   <<<(E + 255) / 256, 256>>>(ei, E);
    k_gather<1><<<(NN * (HH / 4) + 255) / 256, 256>>>(b1, nullptr);
    // layer 2
    k_gemm_mma<2><<<dim3(DOUT / 128, MB), 256, SMEM>>>(nullptr);
    k_gather<2><<<(NN * (DOUT / 4) + 255) / 256, 256>>>(b2, out);
}

// round 15
// speedup vs baseline: 1.8286x; 1.1104x over previous
#include <cuda_runtime.h>
#include <cuda_fp16.h>
#include <cstdint>

// Problem shapes (fixed for GCNNet_61323543052323)
#define NN   100000
#define FIN  512
#define HH   256
#define DOUT 128
#define EMAX 800000
#define NBLK ((NN + 255) / 256)

// -------------------- scratch (device globals) ------------------------------
__device__ __align__(128) float  g_dinv[NN];
__device__ __align__(128) __half g_hs1 [(size_t)NN * HH];        // GEMM1 out (fp16)
__device__ __align__(128) __half g_hs2 [(size_t)NN * DOUT];      // GEMM2 out (fp16)
__device__ __align__(128) __half g_h1  [(size_t)NN * HH];        // h1 (fp16)
__device__ __align__(128) __half g_w1th[(size_t)HH * FIN];       // W1^T hi [N][K]
__device__ __align__(128) __half g_w1tl[(size_t)HH * FIN];       // W1^T lo (residual)
__device__ __align__(128) __half g_w2th[(size_t)DOUT * HH];
__device__ __align__(128) __half g_w2tl[(size_t)DOUT * HH];
// CSR by destination (segment bases via atomic counter; order irrelevant)
__device__ __align__(128) int g_cnt [NN];
__device__ __align__(128) int g_fill[NN];
__device__ __align__(128) int g_ptr [NN];
__device__ __align__(128) int g_csr [EMAX];
__device__ int g_total;
__device__ int g_is64;

// -------------------- helpers ----------------------------------------------
__device__ __forceinline__ uint32_t smem_u32(const void* p) {
    uint32_t a;
    asm("{ .reg .u64 t; cvta.to.shared.u64 t, %1; cvt.u32.u64 %0, t; }" : "=r"(a) : "l"(p));
    return a;
}
__device__ __forceinline__ void ldmx4(uint32_t* r, uint32_t addr) {
    asm volatile("ldmatrix.sync.aligned.m8n8.x4.shared.b16 {%0,%1,%2,%3}, [%4];"
                 : "=r"(r[0]), "=r"(r[1]), "=r"(r[2]), "=r"(r[3]) : "r"(addr));
}
__device__ __forceinline__ void mma_fp16(float* d, const uint32_t* a, const uint32_t* b) {
    asm volatile(
        "mma.sync.aligned.m16n8k16.row.col.f32.f16.f16.f32 "
        "{%0,%1,%2,%3}, {%4,%5,%6,%7}, {%8,%9}, {%0,%1,%2,%3};"
        : "+f"(d[0]), "+f"(d[1]), "+f"(d[2]), "+f"(d[3])
        : "r"(a[0]), "r"(a[1]), "r"(a[2]), "r"(a[3]), "r"(b[0]), "r"(b[1]));
}
__device__ __forceinline__ void cp16(uint32_t dst, const void* src) {
    asm volatile("cp.async.cg.shared.global [%0], [%1], 16;" :: "r"(dst), "l"(src));
}
__device__ __forceinline__ void cp16p(uint32_t dst, const void* src, int bytes) {
    asm volatile("cp.async.cg.shared.global [%0], [%1], 16, %2;"
                 :: "r"(dst), "l"(src), "r"(bytes));   // bytes==0 -> zero fill
}
__device__ __forceinline__ void cp_commit() { asm volatile("cp.async.commit_group;"); }
__device__ __forceinline__ void cp_wait0()  { asm volatile("cp.async.wait_group 0;" ::: "memory"); }

// pack 8 floats -> 8 fp16 (uint4)
__device__ __forceinline__ uint4 pack8h(const float4& f0, const float4& f1) {
    __half2 a = __float22half2_rn(make_float2(f0.x, f0.y));
    __half2 b = __float22half2_rn(make_float2(f0.z, f0.w));
    __half2 c = __float22half2_rn(make_float2(f1.x, f1.y));
    __half2 d = __float22half2_rn(make_float2(f1.z, f1.w));
    return make_uint4(*(uint32_t*)&a, *(uint32_t*)&b, *(uint32_t*)&c, *(uint32_t*)&d);
}
// unpack 8 fp16 (uint4) -> 8 floats, accumulate
__device__ __forceinline__ void acc8h(float* f, const uint4& u) {
    const __half2* h = (const __half2*)&u;
    float2 t;
    t = __half22float2(h[0]); f[0] += t.x; f[1] += t.y;
    t = __half22float2(h[1]); f[2] += t.x; f[3] += t.y;
    t = __half22float2(h[2]); f[4] += t.x; f[5] += t.y;
    t = __half22float2(h[3]); f[6] += t.x; f[7] += t.y;
}

// -------------------- edge index access ------------------------------------
__device__ __forceinline__ int edge_idx(const void* __restrict__ ei_raw,
                                        int E, int which, int e) {
    long long v;
    if (g_is64) v = ((const long long*)ei_raw)[(size_t)which * E + e];
    else        v = ((const int*)ei_raw)[(size_t)which * E + e];
    unsigned u = (unsigned)v;
    return (u < NN) ? (int)u : 0;
}

// -------------------- fused preproc 0: zero + detect + both W splits -------
__global__ void k_pre0(const void* __restrict__ ei_raw, int E,
                       const float* __restrict__ W1, const float* __restrict__ W2) {
    int i = blockIdx.x * blockDim.x + threadIdx.x;
    if (i < NN) { g_cnt[i] = 0; g_fill[i] = 0; }
    if (i == 0) g_total = 0;
    if (i < FIN * HH) {
        int k = i / HH, n = i % HH;
        float w = W1[i];
        __half h = __float2half_rn(w);
        __half l = __float2half_rn(w - __half2float(h));
        g_w1th[(size_t)n * FIN + k] = h;
        g_w1tl[(size_t)n * FIN + k] = l;
    }
    if (i < HH * DOUT) {
        int k = i / DOUT, n = i % DOUT;
        float w = W2[i];
        __half h = __float2half_rn(w);
        __half l = __float2half_rn(w - __half2float(h));
        g_w2th[(size_t)n * HH + k] = h;
        g_w2tl[(size_t)n * HH + k] = l;
    }
    if (blockIdx.x == 0) {                     // dtype detect
        const long long* p = (const long long*)ei_raw;
        int bad = 0;
        int n = (E < 1024) ? E : 1024;
        for (int j = threadIdx.x; j < n; j += 256) {
            long long v = p[j];
            if (v < 0 || v >= NN) bad = 1;
        }
        bad = __syncthreads_or(bad);
        if (threadIdx.x == 0) g_is64 = !bad;
    }
}
__global__ void k_hist(const void* __restrict__ ei, int E) {
    int e = blockIdx.x * blockDim.x + threadIdx.x;
    if (e < E) atomicAdd(&g_cnt[edge_idx(ei, E, 1, e)], 1);
}
__global__ void k_ptrdinv() {
    int i = blockIdx.x * blockDim.x + threadIdx.x;
    if (i < NN) {
        int c = g_cnt[i];
        g_ptr[i]  = atomicAdd(&g_total, c);
        g_dinv[i] = rsqrtf(1.0f + (float)c);
    }
}
__global__ void k_fill(const void* __restrict__ ei, int E) {
    int e = blockIdx.x * blockDim.x + threadIdx.x;
    if (e >= E) return;
    int src = edge_idx(ei, E, 0, e);
    int dst = edge_idx(ei, E, 1, e);
    int slot = g_ptr[dst] + atomicAdd(&g_fill[dst], 1);
    if (slot < EMAX) g_csr[slot] = src;
}

// -------------------- fp16 GEMM via mma.sync (HMMA) ------------------------
// C(fp16) = (A @ W) * dinv[row], W exact via hi+lo split, A single fp16.
// D = Ah@Bh + Ah@Bl.  Block 128x128xBK32, 8 warps (4m x 2n), warp 32x64.
// 2-stage pipeline (R10-proven ordering). Stage 30720B: A 0, B_HI 10240, B_LO 20480.
template <int LAYER>
__global__ __launch_bounds__(256, 2)
void k_gemm_mma(const float* __restrict__ x) {
    constexpr int K  = (LAYER == 1) ? FIN : HH;
    constexpr int N  = (LAYER == 1) ? HH  : DOUT;
    constexpr int M  = NN;
    constexpr int BK = 32;
    constexpr int NIT = K / BK;
    constexpr int ASTR = 80;
    constexpr int BHo = 10240, BLo = 20480;
    constexpr int STG = 30720;

    extern __shared__ char smem[];
    const uint32_t sb = smem_u32(smem);

    const __half* __restrict__ Wth = (LAYER == 1) ? g_w1th : g_w2th;
    const __half* __restrict__ Wtl = (LAYER == 1) ? g_w1tl : g_w2tl;
    __half* __restrict__ C0 = (LAYER == 1) ? g_hs1 : g_hs2;

    const int tid  = threadIdx.x;
    const int lane = tid & 31;
    const int wid  = tid >> 5;
    const int wm   = (wid & 3) * 32;
    const int wn   = (wid >> 2) * 64;
    const int m0   = blockIdx.y * 128;
    const int n0   = blockIdx.x * 128;

    const int a_rs = (lane & 7) + ((lane >> 3) & 1) * 8;
    const int a_ch = lane >> 4;
    uint32_t a_base[2];
#pragma unroll
    for (int mt = 0; mt < 2; mt++)
        a_base[mt] = sb + (uint32_t)(wm + mt * 16 + a_rs) * ASTR + a_ch * 16;
    const int b_row = (lane & 7) + (lane >> 4) * 8;
    const int b_ch  = (lane >> 3) & 1;
    uint32_t b_base[4];
#pragma unroll
    for (int p = 0; p < 4; p++)
        b_base[p] = sb + BHo + (uint32_t)(wn + p * 16 + b_row) * ASTR + b_ch * 16;

    float acc[2][8][4];
#pragma unroll
    for (int i = 0; i < 2; i++)
#pragma unroll
        for (int j = 0; j < 8; j++)
#pragma unroll
            for (int q = 0; q < 4; q++) acc[i][j][q] = 0.0f;

    float4 fa[4];                         // layer-1 A register staging

    auto cpa = [&](int it, int st) {
        const int k0 = it * BK;
        const uint32_t base = sb + st * STG;
#pragma unroll
        for (int s = 0; s < 2; s++) {
            int lin = s * 256 + tid;
            int row = lin >> 2, c4 = lin & 3;
            uint32_t off = (uint32_t)row * ASTR + c4 * 16;
            if constexpr (LAYER == 2) {
                int gm = m0 + row;
                int ok = (gm < M) ? 16 : 0;
                cp16p(base + off,
                      (const unsigned short*)g_h1 + (size_t)gm * K + k0 + c4 * 8, ok);
            }
            cp16(base + BHo + off,
                 (const unsigned short*)Wth + (size_t)(n0 + row) * K + k0 + c4 * 8);
            cp16(base + BLo + off,
                 (const unsigned short*)Wtl + (size_t)(n0 + row) * K + k0 + c4 * 8);
        }
        cp_commit();
    };

    auto ldgA = [&](int it) {             // layer-1 only: fp32 A into regs
        if constexpr (LAYER == 1) {
            const int k0 = it * BK;
#pragma unroll
            for (int s = 0; s < 2; s++) {
                int lin = s * 256 + tid;
                int row = lin >> 2, c4 = lin & 3;
                int gm = m0 + row;
                if (gm < M) {
                    fa[s * 2]     = *(const float4*)&x[(size_t)gm * K + k0 + c4 * 8];
                    fa[s * 2 + 1] = *(const float4*)&x[(size_t)gm * K + k0 + c4 * 8 + 4];
                } else {
                    fa[s * 2] = fa[s * 2 + 1] = make_float4(0.f, 0.f, 0.f, 0.f);
                }
            }
        }
    };

    auto stsA = [&](int st) {             // layer-1 only: fp32 -> fp16, store A
        if constexpr (LAYER == 1) {
            char* base = smem + st * STG;
#pragma unroll
            for (int s = 0; s < 2; s++) {
                int lin = s * 256 + tid;
                int row = lin >> 2, c4 = lin & 3;
                uint32_t off = (uint32_t)row * ASTR + c4 * 16;
                *(uint4*)(base + off) = pack8h(fa[s * 2], fa[s * 2 + 1]);
            }
        }
    };

    auto compute = [&](int st) {
        const uint32_t so = st * STG;
#pragma unroll
        for (int ks = 0; ks < 2; ks++) {
            uint32_t ah[2][4], bf[8][2];
            ldmx4(ah[0], a_base[0] + so + ks * 32);
            ldmx4(ah[1], a_base[1] + so + ks * 32);
#pragma unroll
            for (int p = 0; p < 4; p++) {
                uint32_t r[4];
                ldmx4(r, b_base[p] + so + ks * 32);
                bf[2 * p][0] = r[0]; bf[2 * p][1] = r[1];
                bf[2 * p + 1][0] = r[2]; bf[2 * p + 1][1] = r[3];
            }
#pragma unroll
            for (int mt = 0; mt < 2; mt++)
#pragma unroll
                for (int nt = 0; nt < 8; nt++) mma_fp16(acc[mt][nt], ah[mt], bf[nt]);
#pragma unroll
            for (int p = 0; p < 4; p++) {
                uint32_t r[4];
                ldmx4(r, b_base[p] + so + (BLo - BHo) + ks * 32);
                bf[2 * p][0] = r[0]; bf[2 * p][1] = r[1];
                bf[2 * p + 1][0] = r[2]; bf[2 * p + 1][1] = r[3];
            }
#pragma unroll
            for (int mt = 0; mt < 2; mt++)
#pragma unroll
                for (int nt = 0; nt < 8; nt++) mma_fp16(acc[mt][nt], ah[mt], bf[nt]);
        }
    };

    // pipeline: cpa -> ldg -> compute -> sts -> wait0 -> sync
    cpa(0, 0);
    ldgA(0);
    stsA(0);
    cp_wait0();
    __syncthreads();

    int cur = 0;
    for (int it = 1; it < NIT; it++) {
        cpa(it, cur ^ 1);
        ldgA(it);
        compute(cur);
        stsA(cur ^ 1);
        cp_wait0();
        __syncthreads();
        cur ^= 1;
    }
    compute(cur);

    // epilogue: scale + fp16 store (half2 per col pair)
#pragma unroll
    for (int mt = 0; mt < 2; mt++) {
        int r0 = wm + mt * 16 + (lane >> 2);
        int gm0 = m0 + r0;
        int gm1 = gm0 + 8;
        float s0 = (gm0 < M) ? g_dinv[gm0] : 0.0f;
        float s1 = (gm1 < M) ? g_dinv[gm1] : 0.0f;
#pragma unroll
        for (int nt = 0; nt < 8; nt++) {
            int col = n0 + wn + nt * 8 + (lane & 3) * 2;
            if (gm0 < M) {
                __half2 h = __float22half2_rn(
                    make_float2(acc[mt][nt][0] * s0, acc[mt][nt][1] * s0));
                *(__half2*)&C0[(size_t)gm0 * N + col] = h;
            }
            if (gm1 < M) {
                __half2 h = __float22half2_rn(
                    make_float2(acc[mt][nt][2] * s1, acc[mt][nt][3] * s1));
                *(__half2*)&C0[(size_t)gm1 * N + col] = h;
            }
        }
    }
}

// -------------------- fused gather-aggregate + bias (+relu/fp16) -----------
// fp16 hs rows; 8 cols per thread (one uint4 per row access); fp32 accum.
template <int LAYER>
__global__ void k_gather(const float* __restrict__ bias, float* __restrict__ out_param) {
    constexpr int NC = (LAYER == 1) ? HH : DOUT;
    constexpr int CH = NC / 8;
    const __half* __restrict__ hs = (LAYER == 1) ? g_hs1 : g_hs2;

    int gtid = blockIdx.x * blockDim.x + threadIdx.x;
    int node = gtid / CH;
    if (node >= NN) return;
    int c = (gtid % CH) * 8;

    float v[8] = {0.f, 0.f, 0.f, 0.f, 0.f, 0.f, 0.f, 0.f};
    acc8h(v, *(const uint4*)&hs[(size_t)node * NC + c]);      // self loop
    int beg = g_ptr[node];
    int end = beg + g_cnt[node];
    int j = beg;
    for (; j + 1 < end; j += 2) {
        int s0 = g_csr[j], s1 = g_csr[j + 1];
        uint4 a = *(const uint4*)&hs[(size_t)s0 * NC + c];
        uint4 b = *(const uint4*)&hs[(size_t)s1 * NC + c];
        acc8h(v, a);
        acc8h(v, b);
    }
    if (j < end)
        acc8h(v, *(const uint4*)&hs[(size_t)g_csr[j] * NC + c]);

    float s = g_dinv[node];
    float r[8];
#pragma unroll
    for (int q = 0; q < 8; q++) r[q] = fmaf(v[q], s, bias[c + q]);

    if (LAYER == 1) {
#pragma unroll
        for (int q = 0; q < 8; q++) r[q] = fmaxf(r[q], 0.f);
        *(uint4*)((unsigned short*)g_h1 + (size_t)node * NC + c) =
            pack8h(make_float4(r[0], r[1], r[2], r[3]),
                   make_float4(r[4], r[5], r[6], r[7]));
    } else {
        float4 o0 = make_float4(r[0], r[1], r[2], r[3]);
        float4 o1 = make_float4(r[4], r[5], r[6], r[7]);
        *(float4*)&out_param[(size_t)node * NC + c]     = o0;
        *(float4*)&out_param[(size_t)node * NC + c + 4] = o1;
    }
}

// ---------------------------------------------------------------------------
extern "C" void kernel_launch(void* const* d_in, const int* in_sizes, int n_in,
                              void* d_out, int out_size) {
    const float* x  = (const float*)d_in[0];
    const void*  ei = d_in[1];
    const float* W1 = (const float*)d_in[2];
    const float* b1 = (const float*)d_in[3];
    const float* W2 = (const float*)d_in[4];
    const float* b2 = (const float*)d_in[5];
    float*       out = (float*)d_out;

    const int E = in_sizes[1] / 2;
    const int MB = (NN + 127) / 128;
    const int SMEM = 2 * 30720;                       // 61440 per CTA, 2 CTAs/SM
    const int PRE0_BLK = (FIN * HH + 255) / 256;

    cudaFuncSetAttribute(k_gemm_mma<1>, cudaFuncAttributeMaxDynamicSharedMemorySize, SMEM);
    cudaFuncSetAttribute(k_gemm_mma<2>, cudaFuncAttributeMaxDynamicSharedMemorySize, SMEM);

    // preproc
    k_pre0   <<<PRE0_BLK, 256>>>(ei, E, W1, W2);
    k_hist   <<<(E + 255) / 256, 256>>>(ei, E);
    k_ptrdinv<<<NBLK, 256>>>();

    // layer 1 (GEMM independent of CSR fill)
    k_gemm_mma<1><<<dim3(HH / 128, MB), 256, SMEM>>>(x);
    k_fill   <<<(E + 255) / 256, 256>>>(ei, E);
    k_gather<1><<<(NN * (HH / 8) + 255) / 256, 256>>>(b1, nullptr);
    // layer 2
    k_gemm_mma<2><<<dim3(DOUT / 128, MB), 256, SMEM>>>(nullptr);
    k_gather<2><<<(NN * (DOUT / 8) + 255) / 256, 256>>>(b2, out);
}

// round 16
// speedup vs baseline: 2.3044x; 1.2602x over previous
#include <cuda_runtime.h>
#include <cuda_fp16.h>
#include <cstdint>

// Problem shapes (fixed for GCNNet_61323543052323)
#define NN   100000
#define FIN  512
#define HH   256
#define DOUT 128
#define EMAX 800000
#define NBLK ((NN + 255) / 256)

// -------------------- scratch (device globals) ------------------------------
__device__ __align__(128) float  g_dinv[NN];
__device__ __align__(128) __half g_hs1 [(size_t)NN * HH];        // GEMM1 out (fp16)
__device__ __align__(128) __half g_hs2 [(size_t)NN * DOUT];      // GEMM2 out (fp16)
__device__ __align__(128) __half g_h1  [(size_t)NN * HH];        // h1 (fp16)
__device__ __align__(128) __half g_w1t [(size_t)HH * FIN];       // W1^T [N][K] fp16
__device__ __align__(128) __half g_w2t [(size_t)DOUT * HH];      // W2^T [N][K] fp16
// CSR by destination (segment bases via atomic counter; order irrelevant)
__device__ __align__(128) int g_cnt [NN];
__device__ __align__(128) int g_fill[NN];
__device__ __align__(128) int g_ptr [NN];
__device__ __align__(128) int g_csr [EMAX];
__device__ int g_total;
__device__ int g_is64;

// -------------------- helpers ----------------------------------------------
__device__ __forceinline__ uint32_t smem_u32(const void* p) {
    uint32_t a;
    asm("{ .reg .u64 t; cvta.to.shared.u64 t, %1; cvt.u32.u64 %0, t; }" : "=r"(a) : "l"(p));
    return a;
}
__device__ __forceinline__ void ldmx4(uint32_t* r, uint32_t addr) {
    asm volatile("ldmatrix.sync.aligned.m8n8.x4.shared.b16 {%0,%1,%2,%3}, [%4];"
                 : "=r"(r[0]), "=r"(r[1]), "=r"(r[2]), "=r"(r[3]) : "r"(addr));
}
__device__ __forceinline__ void mma_fp16(float* d, const uint32_t* a, const uint32_t* b) {
    asm volatile(
        "mma.sync.aligned.m16n8k16.row.col.f32.f16.f16.f32 "
        "{%0,%1,%2,%3}, {%4,%5,%6,%7}, {%8,%9}, {%0,%1,%2,%3};"
        : "+f"(d[0]), "+f"(d[1]), "+f"(d[2]), "+f"(d[3])
        : "r"(a[0]), "r"(a[1]), "r"(a[2]), "r"(a[3]), "r"(b[0]), "r"(b[1]));
}
__device__ __forceinline__ void cp16(uint32_t dst, const void* src) {
    asm volatile("cp.async.cg.shared.global [%0], [%1], 16;" :: "r"(dst), "l"(src));
}
__device__ __forceinline__ void cp16p(uint32_t dst, const void* src, int bytes) {
    asm volatile("cp.async.cg.shared.global [%0], [%1], 16, %2;"
                 :: "r"(dst), "l"(src), "r"(bytes));   // bytes==0 -> zero fill
}
__device__ __forceinline__ void cp_commit() { asm volatile("cp.async.commit_group;"); }
__device__ __forceinline__ void cp_wait0()  { asm volatile("cp.async.wait_group 0;" ::: "memory"); }

// pack 8 floats -> 8 fp16 (uint4)
__device__ __forceinline__ uint4 pack8h(const float4& f0, const float4& f1) {
    __half2 a = __float22half2_rn(make_float2(f0.x, f0.y));
    __half2 b = __float22half2_rn(make_float2(f0.z, f0.w));
    __half2 c = __float22half2_rn(make_float2(f1.x, f1.y));
    __half2 d = __float22half2_rn(make_float2(f1.z, f1.w));
    return make_uint4(*(uint32_t*)&a, *(uint32_t*)&b, *(uint32_t*)&c, *(uint32_t*)&d);
}
// unpack 8 fp16 (uint4) -> 8 floats, accumulate
__device__ __forceinline__ void acc8h(float* f, const uint4& u) {
    const __half2* h = (const __half2*)&u;
    float2 t;
    t = __half22float2(h[0]); f[0] += t.x; f[1] += t.y;
    t = __half22float2(h[1]); f[2] += t.x; f[3] += t.y;
    t = __half22float2(h[2]); f[4] += t.x; f[5] += t.y;
    t = __half22float2(h[3]); f[6] += t.x; f[7] += t.y;
}

// -------------------- edge index access ------------------------------------
__device__ __forceinline__ int edge_idx(const void* __restrict__ ei_raw,
                                        int E, int which, int e) {
    long long v;
    if (g_is64) v = ((const long long*)ei_raw)[(size_t)which * E + e];
    else        v = ((const int*)ei_raw)[(size_t)which * E + e];
    unsigned u = (unsigned)v;
    return (u < NN) ? (int)u : 0;
}

// -------------------- fused preproc 0: zero + detect + W transposes --------
__global__ void k_pre0(const void* __restrict__ ei_raw, int E,
                       const float* __restrict__ W1, const float* __restrict__ W2) {
    int i = blockIdx.x * blockDim.x + threadIdx.x;
    if (i < NN) { g_cnt[i] = 0; g_fill[i] = 0; }
    if (i == 0) g_total = 0;
    if (i < FIN * HH) {
        int k = i / HH, n = i % HH;
        g_w1t[(size_t)n * FIN + k] = __float2half_rn(W1[i]);
    }
    if (i < HH * DOUT) {
        int k = i / DOUT, n = i % DOUT;
        g_w2t[(size_t)n * HH + k] = __float2half_rn(W2[i]);
    }
    if (blockIdx.x == 0) {                     // dtype detect
        const long long* p = (const long long*)ei_raw;
        int bad = 0;
        int n = (E < 1024) ? E : 1024;
        for (int j = threadIdx.x; j < n; j += 256) {
            long long v = p[j];
            if (v < 0 || v >= NN) bad = 1;
        }
        bad = __syncthreads_or(bad);
        if (threadIdx.x == 0) g_is64 = !bad;
    }
}
__global__ void k_hist(const void* __restrict__ ei, int E) {
    int e = blockIdx.x * blockDim.x + threadIdx.x;
    if (e < E) atomicAdd(&g_cnt[edge_idx(ei, E, 1, e)], 1);
}
__global__ void k_ptrdinv() {
    int i = blockIdx.x * blockDim.x + threadIdx.x;
    if (i < NN) {
        int c = g_cnt[i];
        g_ptr[i]  = atomicAdd(&g_total, c);
        g_dinv[i] = rsqrtf(1.0f + (float)c);
    }
}
__global__ void k_fill(const void* __restrict__ ei, int E) {
    int e = blockIdx.x * blockDim.x + threadIdx.x;
    if (e >= E) return;
    int src = edge_idx(ei, E, 0, e);
    int dst = edge_idx(ei, E, 1, e);
    int slot = g_ptr[dst] + atomicAdd(&g_fill[dst], 1);
    if (slot < EMAX) g_csr[slot] = src;
}

// -------------------- fp16 GEMM via mma.sync (HMMA) ------------------------
// C(fp16) = (A @ W) * dinv[row], A and W single fp16, fp32 accumulate.
// Block 128x128xBK32, 8 warps (4m x 2n), warp 32x64.
// 2-stage pipeline (R10-proven ordering). Stage 20480B: A 0, B 10240.
template <int LAYER>
__global__ __launch_bounds__(256, 2)
void k_gemm_mma(const float* __restrict__ x) {
    constexpr int K  = (LAYER == 1) ? FIN : HH;
    constexpr int N  = (LAYER == 1) ? HH  : DOUT;
    constexpr int M  = NN;
    constexpr int BK = 32;
    constexpr int NIT = K / BK;
    constexpr int ASTR = 80;
    constexpr int BO  = 10240;
    constexpr int STG = 20480;

    extern __shared__ char smem[];
    const uint32_t sb = smem_u32(smem);

    const __half* __restrict__ Wt = (LAYER == 1) ? g_w1t : g_w2t;
    __half* __restrict__ C0 = (LAYER == 1) ? g_hs1 : g_hs2;

    const int tid  = threadIdx.x;
    const int lane = tid & 31;
    const int wid  = tid >> 5;
    const int wm   = (wid & 3) * 32;
    const int wn   = (wid >> 2) * 64;
    const int m0   = blockIdx.y * 128;
    const int n0   = blockIdx.x * 128;

    const int a_rs = (lane & 7) + ((lane >> 3) & 1) * 8;
    const int a_ch = lane >> 4;
    uint32_t a_base[2];
#pragma unroll
    for (int mt = 0; mt < 2; mt++)
        a_base[mt] = sb + (uint32_t)(wm + mt * 16 + a_rs) * ASTR + a_ch * 16;
    const int b_row = (lane & 7) + (lane >> 4) * 8;
    const int b_ch  = (lane >> 3) & 1;
    uint32_t b_base[4];
#pragma unroll
    for (int p = 0; p < 4; p++)
        b_base[p] = sb + BO + (uint32_t)(wn + p * 16 + b_row) * ASTR + b_ch * 16;

    float acc[2][8][4];
#pragma unroll
    for (int i = 0; i < 2; i++)
#pragma unroll
        for (int j = 0; j < 8; j++)
#pragma unroll
            for (int q = 0; q < 4; q++) acc[i][j][q] = 0.0f;

    float4 fa[4];                         // layer-1 A register staging

    auto cpa = [&](int it, int st) {
        const int k0 = it * BK;
        const uint32_t base = sb + st * STG;
#pragma unroll
        for (int s = 0; s < 2; s++) {
            int lin = s * 256 + tid;
            int row = lin >> 2, c4 = lin & 3;
            uint32_t off = (uint32_t)row * ASTR + c4 * 16;
            if constexpr (LAYER == 2) {
                int gm = m0 + row;
                int ok = (gm < M) ? 16 : 0;
                cp16p(base + off,
                      (const unsigned short*)g_h1 + (size_t)gm * K + k0 + c4 * 8, ok);
            }
            cp16(base + BO + off,
                 (const unsigned short*)Wt + (size_t)(n0 + row) * K + k0 + c4 * 8);
        }
        cp_commit();
    };

    auto ldgA = [&](int it) {             // layer-1 only: fp32 A into regs
        if constexpr (LAYER == 1) {
            const int k0 = it * BK;
#pragma unroll
            for (int s = 0; s < 2; s++) {
                int lin = s * 256 + tid;
                int row = lin >> 2, c4 = lin & 3;
                int gm = m0 + row;
                if (gm < M) {
                    fa[s * 2]     = *(const float4*)&x[(size_t)gm * K + k0 + c4 * 8];
                    fa[s * 2 + 1] = *(const float4*)&x[(size_t)gm * K + k0 + c4 * 8 + 4];
                } else {
                    fa[s * 2] = fa[s * 2 + 1] = make_float4(0.f, 0.f, 0.f, 0.f);
                }
            }
        }
    };

    auto stsA = [&](int st) {             // layer-1 only: fp32 -> fp16, store A
        if constexpr (LAYER == 1) {
            char* base = smem + st * STG;
#pragma unroll
            for (int s = 0; s < 2; s++) {
                int lin = s * 256 + tid;
                int row = lin >> 2, c4 = lin & 3;
                uint32_t off = (uint32_t)row * ASTR + c4 * 16;
                *(uint4*)(base + off) = pack8h(fa[s * 2], fa[s * 2 + 1]);
            }
        }
    };

    auto compute = [&](int st) {
        const uint32_t so = st * STG;
#pragma unroll
        for (int ks = 0; ks < 2; ks++) {
            uint32_t ah[2][4], bf[8][2];
            ldmx4(ah[0], a_base[0] + so + ks * 32);
            ldmx4(ah[1], a_base[1] + so + ks * 32);
#pragma unroll
            for (int p = 0; p < 4; p++) {
                uint32_t r[4];
                ldmx4(r, b_base[p] + so + ks * 32);
                bf[2 * p][0] = r[0]; bf[2 * p][1] = r[1];
                bf[2 * p + 1][0] = r[2]; bf[2 * p + 1][1] = r[3];
            }
#pragma unroll
            for (int mt = 0; mt < 2; mt++)
#pragma unroll
                for (int nt = 0; nt < 8; nt++) mma_fp16(acc[mt][nt], ah[mt], bf[nt]);
        }
    };

    // pipeline: cpa -> ldg -> compute -> sts -> wait0 -> sync
    cpa(0, 0);
    ldgA(0);
    stsA(0);
    cp_wait0();
    __syncthreads();

    int cur = 0;
    for (int it = 1; it < NIT; it++) {
        cpa(it, cur ^ 1);
        ldgA(it);
        compute(cur);
        stsA(cur ^ 1);
        cp_wait0();
        __syncthreads();
        cur ^= 1;
    }
    compute(cur);

    // epilogue: scale + fp16 store (half2 per col pair)
#pragma unroll
    for (int mt = 0; mt < 2; mt++) {
        int r0 = wm + mt * 16 + (lane >> 2);
        int gm0 = m0 + r0;
        int gm1 = gm0 + 8;
        float s0 = (gm0 < M) ? g_dinv[gm0] : 0.0f;
        float s1 = (gm1 < M) ? g_dinv[gm1] : 0.0f;
#pragma unroll
        for (int nt = 0; nt < 8; nt++) {
            int col = n0 + wn + nt * 8 + (lane & 3) * 2;
            if (gm0 < M) {
                __half2 h = __float22half2_rn(
                    make_float2(acc[mt][nt][0] * s0, acc[mt][nt][1] * s0));
                *(__half2*)&C0[(size_t)gm0 * N + col] = h;
            }
            if (gm1 < M) {
                __half2 h = __float22half2_rn(
                    make_float2(acc[mt][nt][2] * s1, acc[mt][nt][3] * s1));
                *(__half2*)&C0[(size_t)gm1 * N + col] = h;
            }
        }
    }
}

// -------------------- fused gather-aggregate + bias (+relu/fp16) -----------
// fp16 hs rows; 8 cols per thread (one uint4 per row access); fp32 accum.
template <int LAYER>
__global__ void k_gather(const float* __restrict__ bias, float* __restrict__ out_param) {
    constexpr int NC = (LAYER == 1) ? HH : DOUT;
    constexpr int CH = NC / 8;
    const __half* __restrict__ hs = (LAYER == 1) ? g_hs1 : g_hs2;

    int gtid = blockIdx.x * blockDim.x + threadIdx.x;
    int node = gtid / CH;
    if (node >= NN) return;
    int c = (gtid % CH) * 8;

    float v[8] = {0.f, 0.f, 0.f, 0.f, 0.f, 0.f, 0.f, 0.f};
    acc8h(v, *(const uint4*)&hs[(size_t)node * NC + c]);      // self loop
    int beg = g_ptr[node];
    int end = beg + g_cnt[node];
    int j = beg;
    for (; j + 1 < end; j += 2) {
        int s0 = g_csr[j], s1 = g_csr[j + 1];
        uint4 a = *(const uint4*)&hs[(size_t)s0 * NC + c];
        uint4 b = *(const uint4*)&hs[(size_t)s1 * NC + c];
        acc8h(v, a);
        acc8h(v, b);
    }
    if (j < end)
        acc8h(v, *(const uint4*)&hs[(size_t)g_csr[j] * NC + c]);

    float s = g_dinv[node];
    float r[8];
#pragma unroll
    for (int q = 0; q < 8; q++) r[q] = fmaf(v[q], s, bias[c + q]);

    if (LAYER == 1) {
#pragma unroll
        for (int q = 0; q < 8; q++) r[q] = fmaxf(r[q], 0.f);
        *(uint4*)((unsigned short*)g_h1 + (size_t)node * NC + c) =
            pack8h(make_float4(r[0], r[1], r[2], r[3]),
                   make_float4(r[4], r[5], r[6], r[7]));
    } else {
        float4 o0 = make_float4(r[0], r[1], r[2], r[3]);
        float4 o1 = make_float4(r[4], r[5], r[6], r[7]);
        *(float4*)&out_param[(size_t)node * NC + c]     = o0;
        *(float4*)&out_param[(size_t)node * NC + c + 4] = o1;
    }
}

// ---------------------------------------------------------------------------
extern "C" void kernel_launch(void* const* d_in, const int* in_sizes, int n_in,
                              void* d_out, int out_size) {
    const float* x  = (const float*)d_in[0];
    const void*  ei = d_in[1];
    const float* W1 = (const float*)d_in[2];
    const float* b1 = (const float*)d_in[3];
    const float* W2 = (const float*)d_in[4];
    const float* b2 = (const float*)d_in[5];
    float*       out = (float*)d_out;

    const int E = in_sizes[1] / 2;
    const int MB = (NN + 127) / 128;
    const int SMEM = 2 * 20480;                       // 40960 per CTA, 2 CTAs/SM
    const int PRE0_BLK = (FIN * HH + 255) / 256;

    cudaFuncSetAttribute(k_gemm_mma<1>, cudaFuncAttributeMaxDynamicSharedMemorySize, SMEM);
    cudaFuncSetAttribute(k_gemm_mma<2>, cudaFuncAttributeMaxDynamicSharedMemorySize, SMEM);

    // preproc
    k_pre0   <<<PRE0_BLK, 256>>>(ei, E, W1, W2);
    k_hist   <<<(E + 255) / 256, 256>>>(ei, E);
    k_ptrdinv<<<NBLK, 256>>>();

    // layer 1 (GEMM independent of CSR fill)
    k_gemm_mma<1><<<dim3(HH / 128, MB), 256, SMEM>>>(x);
    k_fill   <<<(E + 255) / 256, 256>>>(ei, E);
    k_gather<1><<<(NN * (HH / 8) + 255) / 256, 256>>>(b1, nullptr);
    // layer 2
    k_gemm_mma<2><<<dim3(DOUT / 128, MB), 256, SMEM>>>(nullptr);
    k_gather<2><<<(NN * (DOUT / 8) + 255) / 256, 256>>>(b2, out);
}

// round 17
// speedup vs baseline: 2.3072x; 1.0012x over previous
#include <cuda_runtime.h>
#include <cuda_fp16.h>
#include <cstdint>

// Problem shapes (fixed for GCNNet_61323543052323)
#define NN   100000
#define FIN  512
#define HH   256
#define DOUT 128
#define EMAX 800000
#define NBLK ((NN + 255) / 256)

// -------------------- scratch (device globals) ------------------------------
__device__ __align__(128) float  g_dinv[NN];
__device__ __align__(128) __half g_hs1 [(size_t)NN * HH];        // GEMM1 out (fp16)
__device__ __align__(128) __half g_hs2 [(size_t)NN * DOUT];      // GEMM2 out (fp16)
__device__ __align__(128) __half g_h1  [(size_t)NN * HH];        // h1 (fp16)
__device__ __align__(128) __half g_w1t [(size_t)HH * FIN];       // W1^T [N][K] fp16
__device__ __align__(128) __half g_w2t [(size_t)DOUT * HH];      // W2^T [N][K] fp16
// CSR by destination (segment bases via atomic counter; order irrelevant)
__device__ __align__(128) int g_cnt [NN];
__device__ __align__(128) int g_fill[NN];
__device__ __align__(128) int g_ptr [NN];
__device__ __align__(128) int g_csr [EMAX];
__device__ int g_total;
__device__ int g_is64;

// -------------------- helpers ----------------------------------------------
__device__ __forceinline__ uint32_t smem_u32(const void* p) {
    uint32_t a;
    asm("{ .reg .u64 t; cvta.to.shared.u64 t, %1; cvt.u32.u64 %0, t; }" : "=r"(a) : "l"(p));
    return a;
}
__device__ __forceinline__ void ldmx4(uint32_t* r, uint32_t addr) {
    asm volatile("ldmatrix.sync.aligned.m8n8.x4.shared.b16 {%0,%1,%2,%3}, [%4];"
                 : "=r"(r[0]), "=r"(r[1]), "=r"(r[2]), "=r"(r[3]) : "r"(addr));
}
__device__ __forceinline__ void mma_fp16(float* d, const uint32_t* a, const uint32_t* b) {
    asm volatile(
        "mma.sync.aligned.m16n8k16.row.col.f32.f16.f16.f32 "
        "{%0,%1,%2,%3}, {%4,%5,%6,%7}, {%8,%9}, {%0,%1,%2,%3};"
        : "+f"(d[0]), "+f"(d[1]), "+f"(d[2]), "+f"(d[3])
        : "r"(a[0]), "r"(a[1]), "r"(a[2]), "r"(a[3]), "r"(b[0]), "r"(b[1]));
}
__device__ __forceinline__ void cp16(uint32_t dst, const void* src) {
    asm volatile("cp.async.cg.shared.global [%0], [%1], 16;" :: "r"(dst), "l"(src));
}
__device__ __forceinline__ void cp16p(uint32_t dst, const void* src, int bytes) {
    asm volatile("cp.async.cg.shared.global [%0], [%1], 16, %2;"
                 :: "r"(dst), "l"(src), "r"(bytes));   // bytes==0 -> zero fill
}
__device__ __forceinline__ void cp_commit() { asm volatile("cp.async.commit_group;"); }
__device__ __forceinline__ void cp_wait0()  { asm volatile("cp.async.wait_group 0;" ::: "memory"); }

// pack 8 floats -> 8 fp16 (uint4)
__device__ __forceinline__ uint4 pack8h(const float4& f0, const float4& f1) {
    __half2 a = __float22half2_rn(make_float2(f0.x, f0.y));
    __half2 b = __float22half2_rn(make_float2(f0.z, f0.w));
    __half2 c = __float22half2_rn(make_float2(f1.x, f1.y));
    __half2 d = __float22half2_rn(make_float2(f1.z, f1.w));
    return make_uint4(*(uint32_t*)&a, *(uint32_t*)&b, *(uint32_t*)&c, *(uint32_t*)&d);
}
// unpack 8 fp16 (uint4) -> 8 floats, accumulate
__device__ __forceinline__ void acc8h(float* f, const uint4& u) {
    const __half2* h = (const __half2*)&u;
    float2 t;
    t = __half22float2(h[0]); f[0] += t.x; f[1] += t.y;
    t = __half22float2(h[1]); f[2] += t.x; f[3] += t.y;
    t = __half22float2(h[2]); f[4] += t.x; f[5] += t.y;
    t = __half22float2(h[3]); f[6] += t.x; f[7] += t.y;
}

// -------------------- edge index access ------------------------------------
__device__ __forceinline__ int edge_idx(const void* __restrict__ ei_raw,
                                        int E, int which, int e) {
    long long v;
    if (g_is64) v = ((const long long*)ei_raw)[(size_t)which * E + e];
    else        v = ((const int*)ei_raw)[(size_t)which * E + e];
    unsigned u = (unsigned)v;
    return (u < NN) ? (int)u : 0;
}

// -------------------- fused preproc 0: zero + detect + W transposes --------
__global__ void k_pre0(const void* __restrict__ ei_raw, int E,
                       const float* __restrict__ W1, const float* __restrict__ W2) {
    int i = blockIdx.x * blockDim.x + threadIdx.x;
    if (i < NN) { g_cnt[i] = 0; g_fill[i] = 0; }
    if (i == 0) g_total = 0;
    if (i < FIN * HH) {
        int k = i / HH, n = i % HH;
        g_w1t[(size_t)n * FIN + k] = __float2half_rn(W1[i]);
    }
    if (i < HH * DOUT) {
        int k = i / DOUT, n = i % DOUT;
        g_w2t[(size_t)n * HH + k] = __float2half_rn(W2[i]);
    }
    if (blockIdx.x == 0) {                     // dtype detect
        const long long* p = (const long long*)ei_raw;
        int bad = 0;
        int n = (E < 1024) ? E : 1024;
        for (int j = threadIdx.x; j < n; j += 256) {
            long long v = p[j];
            if (v < 0 || v >= NN) bad = 1;
        }
        bad = __syncthreads_or(bad);
        if (threadIdx.x == 0) g_is64 = !bad;
    }
}
__global__ void k_hist(const void* __restrict__ ei, int E) {
    int e = blockIdx.x * blockDim.x + threadIdx.x;
    if (e < E) atomicAdd(&g_cnt[edge_idx(ei, E, 1, e)], 1);
}
__global__ void k_ptrdinv() {
    int i = blockIdx.x * blockDim.x + threadIdx.x;
    if (i < NN) {
        int c = g_cnt[i];
        g_ptr[i]  = atomicAdd(&g_total, c);
        g_dinv[i] = rsqrtf(1.0f + (float)c);
    }
}
__global__ void k_fill(const void* __restrict__ ei, int E) {
    int e = blockIdx.x * blockDim.x + threadIdx.x;
    if (e >= E) return;
    int src = edge_idx(ei, E, 0, e);
    int dst = edge_idx(ei, E, 1, e);
    int slot = g_ptr[dst] + atomicAdd(&g_fill[dst], 1);
    if (slot < EMAX) g_csr[slot] = src;
}

// -------------------- fp16 GEMM via mma.sync (HMMA) ------------------------
// C(fp16) = (A @ W) * dinv[row], A and W single fp16, fp32 accumulate.
// Block 128x128, 8 warps (4m x 2n), warp 32x64.
// LAYER 1: BK=32 (A fp32->fp16 register-staged).  LAYER 2: BK=64, A via cp.async.
template <int LAYER>
__global__ __launch_bounds__(256, 2)
void k_gemm_mma(const float* __restrict__ x) {
    constexpr int K    = (LAYER == 1) ? FIN : HH;
    constexpr int N    = (LAYER == 1) ? HH  : DOUT;
    constexpr int M    = NN;
    constexpr int BK   = (LAYER == 1) ? 32 : 64;
    constexpr int NIT  = K / BK;
    constexpr int NKS  = BK / 16;                        // ks steps per stage
    constexpr int ASTR = (LAYER == 1) ? 80 : 144;        // row bytes (data + 16 pad)
    constexpr int CPR  = BK / 8;                         // 16B chunks per row
    constexpr int BO   = 128 * ASTR;                     // B tile offset in stage
    constexpr int STG  = 2 * 128 * ASTR;                 // stage size

    extern __shared__ char smem[];
    const uint32_t sb = smem_u32(smem);

    const __half* __restrict__ Wt = (LAYER == 1) ? g_w1t : g_w2t;
    __half* __restrict__ C0 = (LAYER == 1) ? g_hs1 : g_hs2;

    const int tid  = threadIdx.x;
    const int lane = tid & 31;
    const int wid  = tid >> 5;
    const int wm   = (wid & 3) * 32;
    const int wn   = (wid >> 2) * 64;
    const int m0   = blockIdx.y * 128;
    const int n0   = blockIdx.x * 128;

    const int a_rs = (lane & 7) + ((lane >> 3) & 1) * 8;
    const int a_ch = lane >> 4;
    uint32_t a_base[2];
#pragma unroll
    for (int mt = 0; mt < 2; mt++)
        a_base[mt] = sb + (uint32_t)(wm + mt * 16 + a_rs) * ASTR + a_ch * 16;
    const int b_row = (lane & 7) + (lane >> 4) * 8;
    const int b_ch  = (lane >> 3) & 1;
    uint32_t b_base[4];
#pragma unroll
    for (int p = 0; p < 4; p++)
        b_base[p] = sb + BO + (uint32_t)(wn + p * 16 + b_row) * ASTR + b_ch * 16;

    float acc[2][8][4];
#pragma unroll
    for (int i = 0; i < 2; i++)
#pragma unroll
        for (int j = 0; j < 8; j++)
#pragma unroll
            for (int q = 0; q < 4; q++) acc[i][j][q] = 0.0f;

    float4 fa[4];                         // layer-1 A register staging

    auto cpa = [&](int it, int st) {
        const int k0 = it * BK;
        const uint32_t base = sb + st * STG;
        constexpr int NS = 128 * CPR / 256;              // writer passes
#pragma unroll
        for (int s = 0; s < NS; s++) {
            int lin = s * 256 + tid;
            int row = lin / CPR, cc = lin % CPR;
            uint32_t off = (uint32_t)row * ASTR + cc * 16;
            if constexpr (LAYER == 2) {
                int gm = m0 + row;
                int ok = (gm < M) ? 16 : 0;
                cp16p(base + off,
                      (const unsigned short*)g_h1 + (size_t)gm * K + k0 + cc * 8, ok);
            }
            cp16(base + BO + off,
                 (const unsigned short*)Wt + (size_t)(n0 + row) * K + k0 + cc * 8);
        }
        cp_commit();
    };

    auto ldgA = [&](int it) {             // layer-1 only: fp32 A into regs
        if constexpr (LAYER == 1) {
            const int k0 = it * BK;
#pragma unroll
            for (int s = 0; s < 2; s++) {
                int lin = s * 256 + tid;
                int row = lin >> 2, c4 = lin & 3;
                int gm = m0 + row;
                if (gm < M) {
                    fa[s * 2]     = *(const float4*)&x[(size_t)gm * K + k0 + c4 * 8];
                    fa[s * 2 + 1] = *(const float4*)&x[(size_t)gm * K + k0 + c4 * 8 + 4];
                } else {
                    fa[s * 2] = fa[s * 2 + 1] = make_float4(0.f, 0.f, 0.f, 0.f);
                }
            }
        }
    };

    auto stsA = [&](int st) {             // layer-1 only: fp32 -> fp16, store A
        if constexpr (LAYER == 1) {
            char* base = smem + st * STG;
#pragma unroll
            for (int s = 0; s < 2; s++) {
                int lin = s * 256 + tid;
                int row = lin >> 2, c4 = lin & 3;
                uint32_t off = (uint32_t)row * ASTR + c4 * 16;
                *(uint4*)(base + off) = pack8h(fa[s * 2], fa[s * 2 + 1]);
            }
        }
    };

    auto compute = [&](int st) {
        const uint32_t so = st * STG;
#pragma unroll
        for (int ks = 0; ks < NKS; ks++) {
            uint32_t ah[2][4], bf[8][2];
            ldmx4(ah[0], a_base[0] + so + ks * 32);
            ldmx4(ah[1], a_base[1] + so + ks * 32);
#pragma unroll
            for (int p = 0; p < 4; p++) {
                uint32_t r[4];
                ldmx4(r, b_base[p] + so + ks * 32);
                bf[2 * p][0] = r[0]; bf[2 * p][1] = r[1];
                bf[2 * p + 1][0] = r[2]; bf[2 * p + 1][1] = r[3];
            }
#pragma unroll
            for (int mt = 0; mt < 2; mt++)
#pragma unroll
                for (int nt = 0; nt < 8; nt++) mma_fp16(acc[mt][nt], ah[mt], bf[nt]);
        }
    };

    // pipeline: cpa -> ldg -> compute -> sts -> wait0 -> sync
    cpa(0, 0);
    ldgA(0);
    stsA(0);
    cp_wait0();
    __syncthreads();

    int cur = 0;
    for (int it = 1; it < NIT; it++) {
        cpa(it, cur ^ 1);
        ldgA(it);
        compute(cur);
        stsA(cur ^ 1);
        cp_wait0();
        __syncthreads();
        cur ^= 1;
    }
    compute(cur);

    // epilogue: scale + fp16 store (half2 per col pair)
#pragma unroll
    for (int mt = 0; mt < 2; mt++) {
        int r0 = wm + mt * 16 + (lane >> 2);
        int gm0 = m0 + r0;
        int gm1 = gm0 + 8;
        float s0 = (gm0 < M) ? g_dinv[gm0] : 0.0f;
        float s1 = (gm1 < M) ? g_dinv[gm1] : 0.0f;
#pragma unroll
        for (int nt = 0; nt < 8; nt++) {
            int col = n0 + wn + nt * 8 + (lane & 3) * 2;
            if (gm0 < M) {
                __half2 h = __float22half2_rn(
                    make_float2(acc[mt][nt][0] * s0, acc[mt][nt][1] * s0));
                *(__half2*)&C0[(size_t)gm0 * N + col] = h;
            }
            if (gm1 < M) {
                __half2 h = __float22half2_rn(
                    make_float2(acc[mt][nt][2] * s1, acc[mt][nt][3] * s1));
                *(__half2*)&C0[(size_t)gm1 * N + col] = h;
            }
        }
    }
}

// -------------------- fused gather-aggregate + bias (+relu/fp16) -----------
// fp16 hs rows; 8 cols per thread (one uint4 per row access); fp32 accum.
// Unrolled x4 for MLP>=4 (hides L2 latency).
template <int LAYER>
__global__ void k_gather(const float* __restrict__ bias, float* __restrict__ out_param) {
    constexpr int NC = (LAYER == 1) ? HH : DOUT;
    constexpr int CH = NC / 8;
    const __half* __restrict__ hs = (LAYER == 1) ? g_hs1 : g_hs2;

    int gtid = blockIdx.x * blockDim.x + threadIdx.x;
    int node = gtid / CH;
    if (node >= NN) return;
    int c = (gtid % CH) * 8;

    float v[8] = {0.f, 0.f, 0.f, 0.f, 0.f, 0.f, 0.f, 0.f};
    acc8h(v, *(const uint4*)&hs[(size_t)node * NC + c]);      // self loop
    int beg = g_ptr[node];
    int end = beg + g_cnt[node];
    int j = beg;
    for (; j + 3 < end; j += 4) {
        int s0 = g_csr[j], s1 = g_csr[j + 1], s2 = g_csr[j + 2], s3 = g_csr[j + 3];
        uint4 a = *(const uint4*)&hs[(size_t)s0 * NC + c];
        uint4 b = *(const uint4*)&hs[(size_t)s1 * NC + c];
        uint4 d = *(const uint4*)&hs[(size_t)s2 * NC + c];
        uint4 e = *(const uint4*)&hs[(size_t)s3 * NC + c];
        acc8h(v, a); acc8h(v, b); acc8h(v, d); acc8h(v, e);
    }
    for (; j < end; j++)
        acc8h(v, *(const uint4*)&hs[(size_t)g_csr[j] * NC + c]);

    float s = g_dinv[node];
    float r[8];
#pragma unroll
    for (int q = 0; q < 8; q++) r[q] = fmaf(v[q], s, bias[c + q]);

    if (LAYER == 1) {
#pragma unroll
        for (int q = 0; q < 8; q++) r[q] = fmaxf(r[q], 0.f);
        *(uint4*)((unsigned short*)g_h1 + (size_t)node * NC + c) =
            pack8h(make_float4(r[0], r[1], r[2], r[3]),
                   make_float4(r[4], r[5], r[6], r[7]));
    } else {
        float4 o0 = make_float4(r[0], r[1], r[2], r[3]);
        float4 o1 = make_float4(r[4], r[5], r[6], r[7]);
        *(float4*)&out_param[(size_t)node * NC + c]     = o0;
        *(float4*)&out_param[(size_t)node * NC + c + 4] = o1;
    }
}

// ---------------------------------------------------------------------------
extern "C" void kernel_launch(void* const* d_in, const int* in_sizes, int n_in,
                              void* d_out, int out_size) {
    const float* x  = (const float*)d_in[0];
    const void*  ei = d_in[1];
    const float* W1 = (const float*)d_in[2];
    const float* b1 = (const float*)d_in[3];
    const float* W2 = (const float*)d_in[4];
    const float* b2 = (const float*)d_in[5];
    float*       out = (float*)d_out;

    const int E = in_sizes[1] / 2;
    const int MB = (NN + 127) / 128;
    const int SMEM1 = 2 * (2 * 128 * 80);             // 40960
    const int SMEM2 = 2 * (2 * 128 * 144);            // 73728
    const int PRE0_BLK = (FIN * HH + 255) / 256;

    cudaFuncSetAttribute(k_gemm_mma<1>, cudaFuncAttributeMaxDynamicSharedMemorySize, SMEM1);
    cudaFuncSetAttribute(k_gemm_mma<2>, cudaFuncAttributeMaxDynamicSharedMemorySize, SMEM2);

    // preproc
    k_pre0   <<<PRE0_BLK, 256>>>(ei, E, W1, W2);
    k_hist   <<<(E + 255) / 256, 256>>>(ei, E);
    k_ptrdinv<<<NBLK, 256>>>();

    // layer 1 (GEMM independent of CSR fill)
    k_gemm_mma<1><<<dim3(HH / 128, MB), 256, SMEM1>>>(x);
    k_fill   <<<(E + 255) / 256, 256>>>(ei, E);
    k_gather<1><<<(NN * (HH / 8) + 255) / 256, 256>>>(b1, nullptr);
    // layer 2
    k_gemm_mma<2><<<dim3(DOUT / 128, MB), 256, SMEM2>>>(nullptr);
    k_gather<2><<<(NN * (DOUT / 8) + 255) / 256, 256>>>(b2, out);
}